// round 2
// baseline (speedup 1.0000x reference)
#include <cuda_runtime.h>
#include <math.h>

#define BB 4
#define TT 1024
#define DD 1024
#define HH 16
#define HDIM 64
#define BT (BB*TT)

// Scratch (device globals: allocation-free per harness rules)
__device__ float g_k[(size_t)BT * DD];
__device__ float g_q[(size_t)BT * DD];
__device__ float g_v[(size_t)BT * DD];
__device__ float g_s[(size_t)BB * HH * TT * TT];   // scores/weights [b,h,kt,qt] (256 MB)
__device__ float g_attn[(size_t)BT * DD];

#define NEG_INF __int_as_float(0xff800000)

// ---------------------------------------------------------------------------
// C[m,n] = sum_k A[m,k] * W[n,k] + bias[n]   (torch Linear: x @ W.T + b)
// A: [M,K] row-major, W: [N,K] row-major. 64x64 tile, 4x4 microtile, TK=16.
// ---------------------------------------------------------------------------
__global__ void gemm_nt(const float* __restrict__ A, const float* __restrict__ W,
                        const float* __restrict__ bias, float* __restrict__ C,
                        int M, int N, int K) {
    __shared__ float As[64][17];
    __shared__ float Ws[64][17];
    const int tx = threadIdx.x, ty = threadIdx.y;
    const int tid = ty * 16 + tx;
    const int m0 = blockIdx.y * 64, n0 = blockIdx.x * 64;

    float acc[4][4] = {};
    for (int k0 = 0; k0 < K; k0 += 16) {
        #pragma unroll
        for (int i = tid; i < 64 * 16; i += 256) {
            int r = i >> 4, c = i & 15;
            As[r][c] = A[(size_t)(m0 + r) * K + k0 + c];
            Ws[r][c] = W[(size_t)(n0 + r) * K + k0 + c];
        }
        __syncthreads();
        #pragma unroll
        for (int kk = 0; kk < 16; kk++) {
            float a[4], w[4];
            #pragma unroll
            for (int i = 0; i < 4; i++) a[i] = As[ty * 4 + i][kk];
            #pragma unroll
            for (int j = 0; j < 4; j++) w[j] = Ws[tx * 4 + j][kk];
            #pragma unroll
            for (int i = 0; i < 4; i++)
                #pragma unroll
                for (int j = 0; j < 4; j++)
                    acc[i][j] += a[i] * w[j];
        }
        __syncthreads();
    }
    #pragma unroll
    for (int i = 0; i < 4; i++) {
        #pragma unroll
        for (int j = 0; j < 4; j++) {
            int m = m0 + ty * 4 + i, n = n0 + tx * 4 + j;
            C[(size_t)m * N + n] = acc[i][j] + bias[n];
        }
    }
}

// ---------------------------------------------------------------------------
// scores[b,h,kt,qt] = sum_i K[b,kt,h,i]*Q[b,qt,h,i]; mask qt>kt -> -inf; /32
// ---------------------------------------------------------------------------
__global__ void scores_kernel(const float* __restrict__ kbuf,
                              const float* __restrict__ qbuf,
                              float* __restrict__ S) {
    const int bh = blockIdx.z;
    const int b = bh >> 4, h = bh & 15;
    const int kt0 = blockIdx.y * 64, qt0 = blockIdx.x * 64;
    float* Sp = S + (size_t)bh * TT * TT;
    const int tx = threadIdx.x, ty = threadIdx.y;

    if (blockIdx.x > blockIdx.y) {  // fully masked tile: qt_min > kt_max
        #pragma unroll
        for (int i = 0; i < 4; i++)
            #pragma unroll
            for (int j = 0; j < 4; j++)
                Sp[(size_t)(kt0 + ty * 4 + i) * TT + qt0 + tx * 4 + j] = NEG_INF;
        return;
    }

    const float* Kp = kbuf + (size_t)b * TT * DD + h * HDIM;
    const float* Qp = qbuf + (size_t)b * TT * DD + h * HDIM;
    __shared__ float Ks[64][17];
    __shared__ float Qs[64][17];
    const int tid = ty * 16 + tx;

    float acc[4][4] = {};
    for (int k0 = 0; k0 < HDIM; k0 += 16) {
        #pragma unroll
        for (int i = tid; i < 64 * 16; i += 256) {
            int r = i >> 4, c = i & 15;
            Ks[r][c] = Kp[(size_t)(kt0 + r) * DD + k0 + c];
            Qs[r][c] = Qp[(size_t)(qt0 + r) * DD + k0 + c];
        }
        __syncthreads();
        #pragma unroll
        for (int kk = 0; kk < 16; kk++) {
            float a[4], w[4];
            #pragma unroll
            for (int i = 0; i < 4; i++) a[i] = Ks[ty * 4 + i][kk];
            #pragma unroll
            for (int j = 0; j < 4; j++) w[j] = Qs[tx * 4 + j][kk];
            #pragma unroll
            for (int i = 0; i < 4; i++)
                #pragma unroll
                for (int j = 0; j < 4; j++)
                    acc[i][j] += a[i] * w[j];
        }
        __syncthreads();
    }
    #pragma unroll
    for (int i = 0; i < 4; i++) {
        #pragma unroll
        for (int j = 0; j < 4; j++) {
            int kt = kt0 + ty * 4 + i, qt = qt0 + tx * 4 + j;
            Sp[(size_t)kt * TT + qt] = (qt > kt) ? NEG_INF : acc[i][j] * 0.03125f;
        }
    }
}

// ---------------------------------------------------------------------------
// In-place softmax over last (contiguous) axis of [B*H*T, T] rows.
// ---------------------------------------------------------------------------
__global__ void softmax_kernel(float* __restrict__ S) {
    float* p = S + (size_t)blockIdx.x * TT;
    const int tid = threadIdx.x;
    const int wid = tid >> 5, lane = tid & 31;
    __shared__ float red[8];

    float v[4];
    float m = NEG_INF;
    #pragma unroll
    for (int i = 0; i < 4; i++) { v[i] = p[tid + i * 256]; m = fmaxf(m, v[i]); }
    #pragma unroll
    for (int o = 16; o > 0; o >>= 1) m = fmaxf(m, __shfl_xor_sync(0xffffffffu, m, o));
    if (lane == 0) red[wid] = m;
    __syncthreads();
    float mm = red[0];
    #pragma unroll
    for (int i = 1; i < 8; i++) mm = fmaxf(mm, red[i]);
    __syncthreads();

    float s = 0.f;
    #pragma unroll
    for (int i = 0; i < 4; i++) { v[i] = __expf(v[i] - mm); s += v[i]; }
    #pragma unroll
    for (int o = 16; o > 0; o >>= 1) s += __shfl_xor_sync(0xffffffffu, s, o);
    if (lane == 0) red[wid] = s;
    __syncthreads();
    float tot = 0.f;
    #pragma unroll
    for (int i = 0; i < 8; i++) tot += red[i];
    float inv = 1.0f / tot;
    #pragma unroll
    for (int i = 0; i < 4; i++) p[tid + i * 256] = v[i] * inv;
}

// ---------------------------------------------------------------------------
// weights_out[b,kt,qt,h] = S[b,h,kt,qt]  (coalesced both sides via SMEM tile)
// ---------------------------------------------------------------------------
__global__ void transpose_w(const float* __restrict__ S, float* __restrict__ Wout) {
    const int bkt = blockIdx.y;           // b*T + kt
    const int b = bkt >> 10, kt = bkt & 1023;
    const int qt0 = blockIdx.x * 64;
    __shared__ float tile[16][65];
    const int tid = threadIdx.x;

    #pragma unroll
    for (int i = tid; i < 1024; i += 256) {
        int h = i >> 6, q = i & 63;
        tile[h][q] = S[((size_t)(b * HH + h) * TT + kt) * TT + qt0 + q];
    }
    __syncthreads();
    #pragma unroll
    for (int i = tid; i < 1024; i += 256) {
        int q = i >> 4, h = i & 15;
        Wout[((size_t)bkt * TT + qt0 + q) * HH + h] = tile[h][q];
    }
}

// ---------------------------------------------------------------------------
// attn[b,kt,h*64+j] = sum_q S[b,h,kt,q] * V[b,q,h*64+j]; K-loop truncated at
// kt_max+1 (weights are exactly 0 beyond the causal boundary).
// ---------------------------------------------------------------------------
__global__ void av_kernel(const float* __restrict__ S, const float* __restrict__ vbuf,
                          float* __restrict__ attn) {
    const int bh = blockIdx.z;
    const int b = bh >> 4, h = bh & 15;
    const int m0 = blockIdx.y * 64;
    const float* A = S + (size_t)bh * TT * TT;
    const float* Bv = vbuf + (size_t)b * TT * DD + h * HDIM;
    float* Cp = attn + (size_t)b * TT * DD + h * HDIM;

    __shared__ float As[64][17];
    __shared__ float Bs[16][65];
    const int tx = threadIdx.x, ty = threadIdx.y;
    const int tid = ty * 16 + tx;

    float acc[4][4] = {};
    const int kend = m0 + 64;  // causal truncation
    for (int k0 = 0; k0 < kend; k0 += 16) {
        #pragma unroll
        for (int i = tid; i < 64 * 16; i += 256) {
            int r = i >> 4, c = i & 15;
            As[r][c] = A[(size_t)(m0 + r) * TT + k0 + c];
        }
        #pragma unroll
        for (int i = tid; i < 16 * 64; i += 256) {
            int r = i >> 6, c = i & 63;
            Bs[r][c] = Bv[(size_t)(k0 + r) * DD + c];
        }
        __syncthreads();
        #pragma unroll
        for (int kk = 0; kk < 16; kk++) {
            float a[4], w[4];
            #pragma unroll
            for (int i = 0; i < 4; i++) a[i] = As[ty * 4 + i][kk];
            #pragma unroll
            for (int j = 0; j < 4; j++) w[j] = Bs[kk][tx * 4 + j];
            #pragma unroll
            for (int i = 0; i < 4; i++)
                #pragma unroll
                for (int j = 0; j < 4; j++)
                    acc[i][j] += a[i] * w[j];
        }
        __syncthreads();
    }
    #pragma unroll
    for (int i = 0; i < 4; i++)
        #pragma unroll
        for (int j = 0; j < 4; j++)
            Cp[(size_t)(m0 + ty * 4 + i) * DD + tx * 4 + j] = acc[i][j];
}

// ---------------------------------------------------------------------------
extern "C" void kernel_launch(void* const* d_in, const int* in_sizes, int n_in,
                              void* d_out, int out_size) {
    const float* x  = (const float*)d_in[0];
    // d_in[1], d_in[2]: unused scalars; d_in[3]: attn_mask (fixed causal, hardcoded)
    const float* Wk = (const float*)d_in[4];
    const float* bk = (const float*)d_in[5];
    const float* Wq = (const float*)d_in[6];
    const float* bq = (const float*)d_in[7];
    const float* Wv = (const float*)d_in[8];
    const float* bv = (const float*)d_in[9];
    const float* Wp = (const float*)d_in[10];
    const float* bp = (const float*)d_in[11];

    float* out  = (float*)d_out;                       // [B,T,D]
    float* wout = out + (size_t)BT * DD;               // [B,T,T,H]

    float *gk, *gq, *gv, *gs, *ga;
    cudaGetSymbolAddress((void**)&gk, g_k);
    cudaGetSymbolAddress((void**)&gq, g_q);
    cudaGetSymbolAddress((void**)&gv, g_v);
    cudaGetSymbolAddress((void**)&gs, g_s);
    cudaGetSymbolAddress((void**)&ga, g_attn);

    dim3 blk(16, 16);
    dim3 gemm_grid(DD / 64, BT / 64);                  // (16, 64)

    gemm_nt<<<gemm_grid, blk>>>(x, Wk, bk, gk, BT, DD, DD);
    gemm_nt<<<gemm_grid, blk>>>(x, Wq, bq, gq, BT, DD, DD);
    gemm_nt<<<gemm_grid, blk>>>(x, Wv, bv, gv, BT, DD, DD);

    dim3 sc_grid(TT / 64, TT / 64, BB * HH);           // (16, 16, 64)
    scores_kernel<<<sc_grid, blk>>>(gk, gq, gs);

    softmax_kernel<<<BB * HH * TT, 256>>>(gs);

    dim3 tr_grid(TT / 64, BB * TT);                    // (16, 4096)
    transpose_w<<<tr_grid, 256>>>(gs, wout);

    dim3 av_grid(1, TT / 64, BB * HH);                 // (1, 16, 64)
    av_kernel<<<av_grid, blk>>>(gs, gv, ga);

    gemm_nt<<<gemm_grid, blk>>>(ga, Wp, bp, out, BT, DD, DD);
}

// round 4
// speedup vs baseline: 1.6589x; 1.6589x over previous
#include <cuda_runtime.h>
#include <cuda_bf16.h>
#include <mma.h>
#include <math.h>

using namespace nvcuda;

#define BB 4
#define TT 1024
#define DD 1024
#define HH 16
#define HDIM 64
#define BT (BB*TT)

// Scratch (device globals: allocation-free per harness rules)
__device__ float g_k[(size_t)BT * DD];
__device__ float g_q[(size_t)BT * DD];
__device__ float g_v[(size_t)BT * DD];
__device__ float g_s[(size_t)BB * HH * TT * TT];   // scores/weights [b,h,kt,qt] (256 MB)
__device__ float g_attn[(size_t)BT * DD];

// bf16 split buffers
__device__ __nv_bfloat16 g_xhi[(size_t)BT * DD];
__device__ __nv_bfloat16 g_xlo[(size_t)BT * DD];
__device__ __nv_bfloat16 g_whi[(size_t)4 * DD * DD];   // Wk,Wq,Wv,Wp
__device__ __nv_bfloat16 g_wlo[(size_t)4 * DD * DD];
__device__ __nv_bfloat16 g_ahi[(size_t)BT * DD];
__device__ __nv_bfloat16 g_alo[(size_t)BT * DD];

#define NEG_INF __int_as_float(0xff800000)

// ---------------------------------------------------------------------------
// fp32 -> bf16 hi/lo split (hi = bf16(v), lo = bf16(v - hi))
// ---------------------------------------------------------------------------
__global__ void cvt_split(const float* __restrict__ in,
                          __nv_bfloat16* __restrict__ hi,
                          __nv_bfloat16* __restrict__ lo, int n4) {
    int i = blockIdx.x * blockDim.x + threadIdx.x;
    if (i >= n4) return;
    float4 v = ((const float4*)in)[i];
    __nv_bfloat16 h0 = __float2bfloat16(v.x);
    __nv_bfloat16 h1 = __float2bfloat16(v.y);
    __nv_bfloat16 h2 = __float2bfloat16(v.z);
    __nv_bfloat16 h3 = __float2bfloat16(v.w);
    __nv_bfloat16 l0 = __float2bfloat16(v.x - __bfloat162float(h0));
    __nv_bfloat16 l1 = __float2bfloat16(v.y - __bfloat162float(h1));
    __nv_bfloat16 l2 = __float2bfloat16(v.z - __bfloat162float(h2));
    __nv_bfloat16 l3 = __float2bfloat16(v.w - __bfloat162float(h3));
    __nv_bfloat162* ph = (__nv_bfloat162*)hi;
    __nv_bfloat162* pl = (__nv_bfloat162*)lo;
    ph[2 * i]     = __nv_bfloat162(h0, h1);
    ph[2 * i + 1] = __nv_bfloat162(h2, h3);
    pl[2 * i]     = __nv_bfloat162(l0, l1);
    pl[2 * i + 1] = __nv_bfloat162(l2, l3);
}

// ---------------------------------------------------------------------------
// C[m,n] = sum_k A[m,k]*W[n,k] with split-bf16 3-term compensation.
// A,W given as bf16 hi/lo pairs, row-major [M,K]/[N,K]. Tensor-core wmma.
// Block tile 128x128, BK=32, 8 warps (warp tile 32x64).
// ---------------------------------------------------------------------------
#define LDT 48   // padded smem leading dim (keeps 32B alignment: 48*2=96B rows)

__global__ __launch_bounds__(256, 1)
void gemm_bf16split(const __nv_bfloat16* __restrict__ Ahi,
                    const __nv_bfloat16* __restrict__ Alo,
                    const __nv_bfloat16* __restrict__ Bhi,
                    const __nv_bfloat16* __restrict__ Blo,
                    float* __restrict__ C, int M, int N, int K) {
    extern __shared__ __nv_bfloat16 smem[];
    __nv_bfloat16* sAhi = smem;                  // 128*LDT
    __nv_bfloat16* sAlo = sAhi + 128 * LDT;
    __nv_bfloat16* sBhi = sAlo + 128 * LDT;
    __nv_bfloat16* sBlo = sBhi + 128 * LDT;

    const int tid = threadIdx.x;
    const int wid = tid >> 5;
    const int warp_m = wid & 3;      // 0..3 -> 32-row slab
    const int warp_n = wid >> 2;     // 0..1 -> 64-col slab
    const int m0 = blockIdx.y * 128, n0 = blockIdx.x * 128;

    wmma::fragment<wmma::accumulator, 16, 16, 16, float> acc[2][4];
    #pragma unroll
    for (int i = 0; i < 2; i++)
        #pragma unroll
        for (int j = 0; j < 4; j++)
            wmma::fill_fragment(acc[i][j], 0.0f);

    for (int k0 = 0; k0 < K; k0 += 32) {
        // load 128x32 bf16 tiles (64B per row = 4 uint4); 512 uint4 per tile
        #pragma unroll
        for (int u = tid; u < 512; u += 256) {
            int r = u >> 2, cq = u & 3;
            size_t offA = (size_t)(m0 + r) * K + k0;
            size_t offB = (size_t)(n0 + r) * K + k0;
            *(uint4*)(&sAhi[r * LDT + cq * 8]) = ((const uint4*)(Ahi + offA))[cq];
            *(uint4*)(&sAlo[r * LDT + cq * 8]) = ((const uint4*)(Alo + offA))[cq];
            *(uint4*)(&sBhi[r * LDT + cq * 8]) = ((const uint4*)(Bhi + offB))[cq];
            *(uint4*)(&sBlo[r * LDT + cq * 8]) = ((const uint4*)(Blo + offB))[cq];
        }
        __syncthreads();

        #pragma unroll
        for (int kk = 0; kk < 32; kk += 16) {
            wmma::fragment<wmma::matrix_a, 16, 16, 16, __nv_bfloat16, wmma::row_major> aHi[2], aLo[2];
            wmma::fragment<wmma::matrix_b, 16, 16, 16, __nv_bfloat16, wmma::col_major> bHi[4], bLo[4];
            #pragma unroll
            for (int i = 0; i < 2; i++) {
                wmma::load_matrix_sync(aHi[i], &sAhi[(warp_m * 32 + i * 16) * LDT + kk], LDT);
                wmma::load_matrix_sync(aLo[i], &sAlo[(warp_m * 32 + i * 16) * LDT + kk], LDT);
            }
            #pragma unroll
            for (int j = 0; j < 4; j++) {
                wmma::load_matrix_sync(bHi[j], &sBhi[(warp_n * 64 + j * 16) * LDT + kk], LDT);
                wmma::load_matrix_sync(bLo[j], &sBlo[(warp_n * 64 + j * 16) * LDT + kk], LDT);
            }
            #pragma unroll
            for (int i = 0; i < 2; i++)
                #pragma unroll
                for (int j = 0; j < 4; j++) {
                    wmma::mma_sync(acc[i][j], aHi[i], bHi[j], acc[i][j]);
                    wmma::mma_sync(acc[i][j], aHi[i], bLo[j], acc[i][j]);
                    wmma::mma_sync(acc[i][j], aLo[i], bHi[j], acc[i][j]);
                }
        }
        __syncthreads();
    }

    #pragma unroll
    for (int i = 0; i < 2; i++)
        #pragma unroll
        for (int j = 0; j < 4; j++) {
            float* cp = C + (size_t)(m0 + warp_m * 32 + i * 16) * N + n0 + warp_n * 64 + j * 16;
            wmma::store_matrix_sync(cp, acc[i][j], N, wmma::mem_row_major);
        }
}

// ---------------------------------------------------------------------------
// C[m,n] += bias[n]  (N = 1024, mask = N/4 - 1)
// ---------------------------------------------------------------------------
__global__ void bias_add(float* __restrict__ C, const float* __restrict__ bias, int total4) {
    int i = blockIdx.x * blockDim.x + threadIdx.x;
    if (i >= total4) return;
    float4 v = ((float4*)C)[i];
    float4 b = ((const float4*)bias)[i & 255];
    v.x += b.x; v.y += b.y; v.z += b.z; v.w += b.w;
    ((float4*)C)[i] = v;
}

// ---------------------------------------------------------------------------
// scores[b,h,kt,qt] = sum_i K[b,kt,h,i]*Q[b,qt,h,i]; mask qt>kt -> -inf; /32
// ---------------------------------------------------------------------------
__global__ void scores_kernel(const float* __restrict__ kbuf,
                              const float* __restrict__ qbuf,
                              float* __restrict__ S) {
    const int bh = blockIdx.z;
    const int b = bh >> 4, h = bh & 15;
    const int kt0 = blockIdx.y * 64, qt0 = blockIdx.x * 64;
    float* Sp = S + (size_t)bh * TT * TT;
    const int tx = threadIdx.x, ty = threadIdx.y;

    if (blockIdx.x > blockIdx.y) {  // fully masked tile
        #pragma unroll
        for (int i = 0; i < 4; i++)
            #pragma unroll
            for (int j = 0; j < 4; j++)
                Sp[(size_t)(kt0 + ty * 4 + i) * TT + qt0 + tx * 4 + j] = NEG_INF;
        return;
    }

    const float* Kp = kbuf + (size_t)b * TT * DD + h * HDIM;
    const float* Qp = qbuf + (size_t)b * TT * DD + h * HDIM;
    __shared__ float Ks[64][17];
    __shared__ float Qs[64][17];
    const int tid = ty * 16 + tx;

    float acc[4][4] = {};
    for (int k0 = 0; k0 < HDIM; k0 += 16) {
        #pragma unroll
        for (int i = tid; i < 64 * 16; i += 256) {
            int r = i >> 4, c = i & 15;
            Ks[r][c] = Kp[(size_t)(kt0 + r) * DD + k0 + c];
            Qs[r][c] = Qp[(size_t)(qt0 + r) * DD + k0 + c];
        }
        __syncthreads();
        #pragma unroll
        for (int kk = 0; kk < 16; kk++) {
            float a[4], w[4];
            #pragma unroll
            for (int i = 0; i < 4; i++) a[i] = Ks[ty * 4 + i][kk];
            #pragma unroll
            for (int j = 0; j < 4; j++) w[j] = Qs[tx * 4 + j][kk];
            #pragma unroll
            for (int i = 0; i < 4; i++)
                #pragma unroll
                for (int j = 0; j < 4; j++)
                    acc[i][j] += a[i] * w[j];
        }
        __syncthreads();
    }
    #pragma unroll
    for (int i = 0; i < 4; i++) {
        #pragma unroll
        for (int j = 0; j < 4; j++) {
            int kt = kt0 + ty * 4 + i, qt = qt0 + tx * 4 + j;
            Sp[(size_t)kt * TT + qt] = (qt > kt) ? NEG_INF : acc[i][j] * 0.03125f;
        }
    }
}

// ---------------------------------------------------------------------------
// In-place softmax over last (contiguous) axis of [B*H*T, T] rows.
// ---------------------------------------------------------------------------
__global__ void softmax_kernel(float* __restrict__ S) {
    float* p = S + (size_t)blockIdx.x * TT;
    const int tid = threadIdx.x;
    const int wid = tid >> 5, lane = tid & 31;
    __shared__ float red[8];

    float v[4];
    float m = NEG_INF;
    #pragma unroll
    for (int i = 0; i < 4; i++) { v[i] = p[tid + i * 256]; m = fmaxf(m, v[i]); }
    #pragma unroll
    for (int o = 16; o > 0; o >>= 1) m = fmaxf(m, __shfl_xor_sync(0xffffffffu, m, o));
    if (lane == 0) red[wid] = m;
    __syncthreads();
    float mm = red[0];
    #pragma unroll
    for (int i = 1; i < 8; i++) mm = fmaxf(mm, red[i]);
    __syncthreads();

    float s = 0.f;
    #pragma unroll
    for (int i = 0; i < 4; i++) { v[i] = __expf(v[i] - mm); s += v[i]; }
    #pragma unroll
    for (int o = 16; o > 0; o >>= 1) s += __shfl_xor_sync(0xffffffffu, s, o);
    if (lane == 0) red[wid] = s;
    __syncthreads();
    float tot = 0.f;
    #pragma unroll
    for (int i = 0; i < 8; i++) tot += red[i];
    float inv = 1.0f / tot;
    #pragma unroll
    for (int i = 0; i < 4; i++) p[tid + i * 256] = v[i] * inv;
}

// ---------------------------------------------------------------------------
// weights_out[b,kt,qt,h] = S[b,h,kt,qt]
// ---------------------------------------------------------------------------
__global__ void transpose_w(const float* __restrict__ S, float* __restrict__ Wout) {
    const int bkt = blockIdx.y;           // b*T + kt
    const int b = bkt >> 10, kt = bkt & 1023;
    const int qt0 = blockIdx.x * 64;
    __shared__ float tile[16][65];
    const int tid = threadIdx.x;

    #pragma unroll
    for (int i = tid; i < 1024; i += 256) {
        int h = i >> 6, q = i & 63;
        tile[h][q] = S[((size_t)(b * HH + h) * TT + kt) * TT + qt0 + q];
    }
    __syncthreads();
    #pragma unroll
    for (int i = tid; i < 1024; i += 256) {
        int q = i >> 4, h = i & 15;
        Wout[((size_t)bkt * TT + qt0 + q) * HH + h] = tile[h][q];
    }
}

// ---------------------------------------------------------------------------
// attn[b,kt,h*64+j] = sum_q S[b,h,kt,q] * V[b,q,h*64+j]; causal K-truncation.
// ---------------------------------------------------------------------------
__global__ void av_kernel(const float* __restrict__ S, const float* __restrict__ vbuf,
                          float* __restrict__ attn) {
    const int bh = blockIdx.z;
    const int b = bh >> 4, h = bh & 15;
    const int m0 = blockIdx.y * 64;
    const float* A = S + (size_t)bh * TT * TT;
    const float* Bv = vbuf + (size_t)b * TT * DD + h * HDIM;
    float* Cp = attn + (size_t)b * TT * DD + h * HDIM;

    __shared__ float As[64][17];
    __shared__ float Bs[16][65];
    const int tx = threadIdx.x, ty = threadIdx.y;
    const int tid = ty * 16 + tx;

    float acc[4][4] = {};
    const int kend = m0 + 64;  // causal truncation
    for (int k0 = 0; k0 < kend; k0 += 16) {
        #pragma unroll
        for (int i = tid; i < 64 * 16; i += 256) {
            int r = i >> 4, c = i & 15;
            As[r][c] = A[(size_t)(m0 + r) * TT + k0 + c];
        }
        #pragma unroll
        for (int i = tid; i < 16 * 64; i += 256) {
            int r = i >> 6, c = i & 63;
            Bs[r][c] = Bv[(size_t)(k0 + r) * DD + c];
        }
        __syncthreads();
        #pragma unroll
        for (int kk = 0; kk < 16; kk++) {
            float a[4], w[4];
            #pragma unroll
            for (int i = 0; i < 4; i++) a[i] = As[ty * 4 + i][kk];
            #pragma unroll
            for (int j = 0; j < 4; j++) w[j] = Bs[kk][tx * 4 + j];
            #pragma unroll
            for (int i = 0; i < 4; i++)
                #pragma unroll
                for (int j = 0; j < 4; j++)
                    acc[i][j] += a[i] * w[j];
        }
        __syncthreads();
    }
    #pragma unroll
    for (int i = 0; i < 4; i++)
        #pragma unroll
        for (int j = 0; j < 4; j++)
            Cp[(size_t)(m0 + ty * 4 + i) * DD + tx * 4 + j] = acc[i][j];
}

// ---------------------------------------------------------------------------
extern "C" void kernel_launch(void* const* d_in, const int* in_sizes, int n_in,
                              void* d_out, int out_size) {
    const float* x  = (const float*)d_in[0];
    const float* Wk = (const float*)d_in[4];
    const float* bk = (const float*)d_in[5];
    const float* Wq = (const float*)d_in[6];
    const float* bq = (const float*)d_in[7];
    const float* Wv = (const float*)d_in[8];
    const float* bv = (const float*)d_in[9];
    const float* Wp = (const float*)d_in[10];
    const float* bp = (const float*)d_in[11];

    float* out  = (float*)d_out;                       // [B,T,D]
    float* wout = out + (size_t)BT * DD;               // [B,T,T,H]

    float *gk, *gq, *gv, *gs, *ga;
    __nv_bfloat16 *xhi, *xlo, *whi, *wlo, *ahi, *alo;
    cudaGetSymbolAddress((void**)&gk, g_k);
    cudaGetSymbolAddress((void**)&gq, g_q);
    cudaGetSymbolAddress((void**)&gv, g_v);
    cudaGetSymbolAddress((void**)&gs, g_s);
    cudaGetSymbolAddress((void**)&ga, g_attn);
    cudaGetSymbolAddress((void**)&xhi, g_xhi);
    cudaGetSymbolAddress((void**)&xlo, g_xlo);
    cudaGetSymbolAddress((void**)&whi, g_whi);
    cudaGetSymbolAddress((void**)&wlo, g_wlo);
    cudaGetSymbolAddress((void**)&ahi, g_ahi);
    cudaGetSymbolAddress((void**)&alo, g_alo);

    const size_t WSZ = (size_t)DD * DD;
    const int n4x = BT * DD / 4;       // 1M
    const int n4w = DD * DD / 4;       // 256K

    // split conversions
    cvt_split<<<(n4x + 255) / 256, 256>>>(x,  xhi, xlo, n4x);
    cvt_split<<<(n4w + 255) / 256, 256>>>(Wk, whi + 0 * WSZ, wlo + 0 * WSZ, n4w);
    cvt_split<<<(n4w + 255) / 256, 256>>>(Wq, whi + 1 * WSZ, wlo + 1 * WSZ, n4w);
    cvt_split<<<(n4w + 255) / 256, 256>>>(Wv, whi + 2 * WSZ, wlo + 2 * WSZ, n4w);
    cvt_split<<<(n4w + 255) / 256, 256>>>(Wp, whi + 3 * WSZ, wlo + 3 * WSZ, n4w);

    // tensor-core QKV GEMMs
    dim3 ggrid(DD / 128, BT / 128);    // (8, 32)
    size_t gsm = 4 * 128 * LDT * sizeof(__nv_bfloat16);   // 49152
    gemm_bf16split<<<ggrid, 256, gsm>>>(xhi, xlo, whi + 0 * WSZ, wlo + 0 * WSZ, gk, BT, DD, DD);
    gemm_bf16split<<<ggrid, 256, gsm>>>(xhi, xlo, whi + 1 * WSZ, wlo + 1 * WSZ, gq, BT, DD, DD);
    gemm_bf16split<<<ggrid, 256, gsm>>>(xhi, xlo, whi + 2 * WSZ, wlo + 2 * WSZ, gv, BT, DD, DD);

    const int t4 = BT * DD / 4;
    bias_add<<<(t4 + 255) / 256, 256>>>(gk, bk, t4);
    bias_add<<<(t4 + 255) / 256, 256>>>(gq, bq, t4);
    bias_add<<<(t4 + 255) / 256, 256>>>(gv, bv, t4);

    // attention
    dim3 blk(16, 16);
    dim3 sc_grid(TT / 64, TT / 64, BB * HH);
    scores_kernel<<<sc_grid, blk>>>(gk, gq, gs);
    softmax_kernel<<<BB * HH * TT, 256>>>(gs);
    dim3 tr_grid(TT / 64, BB * TT);
    transpose_w<<<tr_grid, 256>>>(gs, wout);
    dim3 av_grid(1, TT / 64, BB * HH);
    av_kernel<<<av_grid, blk>>>(gs, gv, ga);

    // projection
    cvt_split<<<(n4x + 255) / 256, 256>>>(ga, ahi, alo, n4x);
    gemm_bf16split<<<ggrid, 256, gsm>>>(ahi, alo, whi + 3 * WSZ, wlo + 3 * WSZ, out, BT, DD, DD);
    bias_add<<<(t4 + 255) / 256, 256>>>(out, bp, t4);
}

// round 5
// speedup vs baseline: 2.5229x; 1.5209x over previous
#include <cuda_runtime.h>
#include <cuda_bf16.h>
#include <mma.h>
#include <math.h>

using namespace nvcuda;

#define BB 4
#define TT 1024
#define DD 1024
#define HH 16
#define HDIM 64
#define BT (BB*TT)

// fp32 scratch
__device__ float g_k[(size_t)BT * DD];
__device__ float g_q[(size_t)BT * DD];
__device__ float g_v[(size_t)BT * DD];
__device__ float g_s[(size_t)BB * HH * TT * TT];   // scores fp32 [b,h,kt,qt] (lower tri only)
__device__ float g_attn[(size_t)BT * DD];

// bf16 split buffers
__device__ __nv_bfloat16 g_xhi[(size_t)BT * DD];
__device__ __nv_bfloat16 g_xlo[(size_t)BT * DD];
__device__ __nv_bfloat16 g_whi[(size_t)4 * DD * DD];
__device__ __nv_bfloat16 g_wlo[(size_t)4 * DD * DD];
__device__ __nv_bfloat16 g_ahi[(size_t)BT * DD];
__device__ __nv_bfloat16 g_alo[(size_t)BT * DD];
__device__ __nv_bfloat16 g_khi[(size_t)BT * DD];
__device__ __nv_bfloat16 g_klo[(size_t)BT * DD];
__device__ __nv_bfloat16 g_qhi[(size_t)BT * DD];
__device__ __nv_bfloat16 g_qlo[(size_t)BT * DD];
__device__ __nv_bfloat16 g_vhi[(size_t)BT * DD];
__device__ __nv_bfloat16 g_vlo[(size_t)BT * DD];
__device__ __nv_bfloat16 g_swhi[(size_t)BB * HH * TT * TT];  // softmax weights hi (128MB)
__device__ __nv_bfloat16 g_swlo[(size_t)BB * HH * TT * TT];  // softmax weights lo

#define NEG_INF __int_as_float(0xff800000)

// ---------------------------------------------------------------------------
__global__ void cvt_split(const float* __restrict__ in,
                          __nv_bfloat16* __restrict__ hi,
                          __nv_bfloat16* __restrict__ lo, int n4) {
    int i = blockIdx.x * blockDim.x + threadIdx.x;
    if (i >= n4) return;
    float4 v = ((const float4*)in)[i];
    __nv_bfloat16 h0 = __float2bfloat16(v.x), h1 = __float2bfloat16(v.y);
    __nv_bfloat16 h2 = __float2bfloat16(v.z), h3 = __float2bfloat16(v.w);
    __nv_bfloat16 l0 = __float2bfloat16(v.x - __bfloat162float(h0));
    __nv_bfloat16 l1 = __float2bfloat16(v.y - __bfloat162float(h1));
    __nv_bfloat16 l2 = __float2bfloat16(v.z - __bfloat162float(h2));
    __nv_bfloat16 l3 = __float2bfloat16(v.w - __bfloat162float(h3));
    ((__nv_bfloat162*)hi)[2*i]   = __nv_bfloat162(h0, h1);
    ((__nv_bfloat162*)hi)[2*i+1] = __nv_bfloat162(h2, h3);
    ((__nv_bfloat162*)lo)[2*i]   = __nv_bfloat162(l0, l1);
    ((__nv_bfloat162*)lo)[2*i+1] = __nv_bfloat162(l2, l3);
}

// ---------------------------------------------------------------------------
// read fp32 gemm out, add bias, write bf16 hi/lo split only
// ---------------------------------------------------------------------------
__global__ void bias_split(const float* __restrict__ in, const float* __restrict__ bias,
                           __nv_bfloat16* __restrict__ hi, __nv_bfloat16* __restrict__ lo,
                           int n4) {
    int i = blockIdx.x * blockDim.x + threadIdx.x;
    if (i >= n4) return;
    float4 v = ((const float4*)in)[i];
    float4 b = ((const float4*)bias)[i & 255];
    v.x += b.x; v.y += b.y; v.z += b.z; v.w += b.w;
    __nv_bfloat16 h0 = __float2bfloat16(v.x), h1 = __float2bfloat16(v.y);
    __nv_bfloat16 h2 = __float2bfloat16(v.z), h3 = __float2bfloat16(v.w);
    __nv_bfloat16 l0 = __float2bfloat16(v.x - __bfloat162float(h0));
    __nv_bfloat16 l1 = __float2bfloat16(v.y - __bfloat162float(h1));
    __nv_bfloat16 l2 = __float2bfloat16(v.z - __bfloat162float(h2));
    __nv_bfloat16 l3 = __float2bfloat16(v.w - __bfloat162float(h3));
    ((__nv_bfloat162*)hi)[2*i]   = __nv_bfloat162(h0, h1);
    ((__nv_bfloat162*)hi)[2*i+1] = __nv_bfloat162(h2, h3);
    ((__nv_bfloat162*)lo)[2*i]   = __nv_bfloat162(l0, l1);
    ((__nv_bfloat162*)lo)[2*i+1] = __nv_bfloat162(l2, l3);
}

// ---------------------------------------------------------------------------
// big GEMM: C = A @ W.T, split-bf16 3-term, 128x128 tile
// ---------------------------------------------------------------------------
#define LDT 48
__global__ __launch_bounds__(256, 1)
void gemm_bf16split(const __nv_bfloat16* __restrict__ Ahi,
                    const __nv_bfloat16* __restrict__ Alo,
                    const __nv_bfloat16* __restrict__ Bhi,
                    const __nv_bfloat16* __restrict__ Blo,
                    float* __restrict__ C, int M, int N, int K) {
    extern __shared__ __nv_bfloat16 smem[];
    __nv_bfloat16* sAhi = smem;
    __nv_bfloat16* sAlo = sAhi + 128 * LDT;
    __nv_bfloat16* sBhi = sAlo + 128 * LDT;
    __nv_bfloat16* sBlo = sBhi + 128 * LDT;

    const int tid = threadIdx.x, wid = tid >> 5;
    const int warp_m = wid & 3, warp_n = wid >> 2;
    const int m0 = blockIdx.y * 128, n0 = blockIdx.x * 128;

    wmma::fragment<wmma::accumulator, 16, 16, 16, float> acc[2][4];
    #pragma unroll
    for (int i = 0; i < 2; i++)
        #pragma unroll
        for (int j = 0; j < 4; j++) wmma::fill_fragment(acc[i][j], 0.0f);

    for (int k0 = 0; k0 < K; k0 += 32) {
        #pragma unroll
        for (int u = tid; u < 512; u += 256) {
            int r = u >> 2, cq = u & 3;
            size_t offA = (size_t)(m0 + r) * K + k0;
            size_t offB = (size_t)(n0 + r) * K + k0;
            *(uint4*)(&sAhi[r * LDT + cq * 8]) = ((const uint4*)(Ahi + offA))[cq];
            *(uint4*)(&sAlo[r * LDT + cq * 8]) = ((const uint4*)(Alo + offA))[cq];
            *(uint4*)(&sBhi[r * LDT + cq * 8]) = ((const uint4*)(Bhi + offB))[cq];
            *(uint4*)(&sBlo[r * LDT + cq * 8]) = ((const uint4*)(Blo + offB))[cq];
        }
        __syncthreads();
        #pragma unroll
        for (int kk = 0; kk < 32; kk += 16) {
            wmma::fragment<wmma::matrix_a, 16, 16, 16, __nv_bfloat16, wmma::row_major> aHi[2], aLo[2];
            wmma::fragment<wmma::matrix_b, 16, 16, 16, __nv_bfloat16, wmma::col_major> bHi[4], bLo[4];
            #pragma unroll
            for (int i = 0; i < 2; i++) {
                wmma::load_matrix_sync(aHi[i], &sAhi[(warp_m * 32 + i * 16) * LDT + kk], LDT);
                wmma::load_matrix_sync(aLo[i], &sAlo[(warp_m * 32 + i * 16) * LDT + kk], LDT);
            }
            #pragma unroll
            for (int j = 0; j < 4; j++) {
                wmma::load_matrix_sync(bHi[j], &sBhi[(warp_n * 64 + j * 16) * LDT + kk], LDT);
                wmma::load_matrix_sync(bLo[j], &sBlo[(warp_n * 64 + j * 16) * LDT + kk], LDT);
            }
            #pragma unroll
            for (int i = 0; i < 2; i++)
                #pragma unroll
                for (int j = 0; j < 4; j++) {
                    wmma::mma_sync(acc[i][j], aHi[i], bHi[j], acc[i][j]);
                    wmma::mma_sync(acc[i][j], aHi[i], bLo[j], acc[i][j]);
                    wmma::mma_sync(acc[i][j], aLo[i], bHi[j], acc[i][j]);
                }
        }
        __syncthreads();
    }
    #pragma unroll
    for (int i = 0; i < 2; i++)
        #pragma unroll
        for (int j = 0; j < 4; j++) {
            float* cp = C + (size_t)(m0 + warp_m * 32 + i * 16) * N + n0 + warp_n * 64 + j * 16;
            wmma::store_matrix_sync(cp, acc[i][j], N, wmma::mem_row_major);
        }
}

// ---------------------------------------------------------------------------
// fp32 bias add for final out
// ---------------------------------------------------------------------------
__global__ void bias_add(float* __restrict__ C, const float* __restrict__ bias, int total4) {
    int i = blockIdx.x * blockDim.x + threadIdx.x;
    if (i >= total4) return;
    float4 v = ((float4*)C)[i];
    float4 b = ((const float4*)bias)[i & 255];
    v.x += b.x; v.y += b.y; v.z += b.z; v.w += b.w;
    ((float4*)C)[i] = v;
}

// ---------------------------------------------------------------------------
// Tensor-core scores: S[bh,kt,qt] = (K·Q)/32 for lower-tri 64x64 blocks.
// 64x64 tile per block, 8 warps (warp tile 16x32), hd=64 single K pass.
// ---------------------------------------------------------------------------
#define LDS 72
__global__ __launch_bounds__(256)
void scores_tc(const __nv_bfloat16* __restrict__ Khi, const __nv_bfloat16* __restrict__ Klo,
               const __nv_bfloat16* __restrict__ Qhi, const __nv_bfloat16* __restrict__ Qlo,
               float* __restrict__ S) {
    if (blockIdx.x > blockIdx.y) return;  // fully masked tile: never read
    __shared__ __nv_bfloat16 sKhi[64 * LDS], sKlo[64 * LDS], sQhi[64 * LDS], sQlo[64 * LDS];
    const int bh = blockIdx.z;
    const int b = bh >> 4, h = bh & 15;
    const int kt0 = blockIdx.y * 64, qt0 = blockIdx.x * 64;
    const int tid = threadIdx.x, wid = tid >> 5;
    const int warp_m = wid >> 1, warp_n = wid & 1;

    const size_t baseK = (size_t)(b * TT + kt0) * DD + h * HDIM;
    const size_t baseQ = (size_t)(b * TT + qt0) * DD + h * HDIM;
    #pragma unroll
    for (int u = tid; u < 512; u += 256) {
        int r = u >> 3, cq = u & 7;
        *(uint4*)(&sKhi[r * LDS + cq * 8]) = ((const uint4*)(Khi + baseK + (size_t)r * DD))[cq];
        *(uint4*)(&sKlo[r * LDS + cq * 8]) = ((const uint4*)(Klo + baseK + (size_t)r * DD))[cq];
        *(uint4*)(&sQhi[r * LDS + cq * 8]) = ((const uint4*)(Qhi + baseQ + (size_t)r * DD))[cq];
        *(uint4*)(&sQlo[r * LDS + cq * 8]) = ((const uint4*)(Qlo + baseQ + (size_t)r * DD))[cq];
    }
    __syncthreads();

    wmma::fragment<wmma::accumulator, 16, 16, 16, float> acc[2];
    wmma::fill_fragment(acc[0], 0.0f);
    wmma::fill_fragment(acc[1], 0.0f);

    #pragma unroll
    for (int kk = 0; kk < 64; kk += 16) {
        wmma::fragment<wmma::matrix_a, 16, 16, 16, __nv_bfloat16, wmma::row_major> aHi, aLo;
        wmma::fragment<wmma::matrix_b, 16, 16, 16, __nv_bfloat16, wmma::col_major> bHi[2], bLo[2];
        wmma::load_matrix_sync(aHi, &sKhi[(warp_m * 16) * LDS + kk], LDS);
        wmma::load_matrix_sync(aLo, &sKlo[(warp_m * 16) * LDS + kk], LDS);
        #pragma unroll
        for (int j = 0; j < 2; j++) {
            wmma::load_matrix_sync(bHi[j], &sQhi[(warp_n * 32 + j * 16) * LDS + kk], LDS);
            wmma::load_matrix_sync(bLo[j], &sQlo[(warp_n * 32 + j * 16) * LDS + kk], LDS);
        }
        #pragma unroll
        for (int j = 0; j < 2; j++) {
            wmma::mma_sync(acc[j], aHi, bHi[j], acc[j]);
            wmma::mma_sync(acc[j], aHi, bLo[j], acc[j]);
            wmma::mma_sync(acc[j], aLo, bHi[j], acc[j]);
        }
    }
    #pragma unroll
    for (int j = 0; j < 2; j++) {
        #pragma unroll
        for (int e = 0; e < acc[j].num_elements; e++) acc[j].x[e] *= 0.03125f;
        float* sp = S + (size_t)bh * TT * TT + (size_t)(kt0 + warp_m * 16) * TT
                      + qt0 + warp_n * 32 + j * 16;
        wmma::store_matrix_sync(sp, acc[j], TT, wmma::mem_row_major);
    }
}

// ---------------------------------------------------------------------------
// Fused: masked softmax over q (q<=kt), write wout[b,kt,q,h] (transposed,
// zeros beyond kt) + bf16 hi/lo weights (zero-padded to next 64 boundary).
// Block = (hgroup of 8, b*T+kt). 256 threads: warp w -> h = hg*8+w.
// ---------------------------------------------------------------------------
__global__ __launch_bounds__(256)
void fused_sm(const float* __restrict__ S, float* __restrict__ wout,
              __nv_bfloat16* __restrict__ whi, __nv_bfloat16* __restrict__ wlo) {
    __shared__ float tile[8][1032];
    const int bkt = blockIdx.y;
    const int b = bkt >> 10, kt = bkt & 1023;
    const int hg = blockIdx.x;
    const int wid = threadIdx.x >> 5, lane = threadIdx.x & 31;
    const int h = hg * 8 + wid;

    const size_t rowoff = ((size_t)(b * HH + h) * TT + kt) * TT;
    const float* row = S + rowoff;
    __nv_bfloat16* hrow = whi + rowoff;
    __nv_bfloat16* lrow = wlo + rowoff;

    float v[32];
    float m = NEG_INF;
    #pragma unroll
    for (int i = 0; i < 32; i++) {
        int q = lane + i * 32;
        if (q <= kt) { v[i] = row[q]; m = fmaxf(m, v[i]); }
        else v[i] = NEG_INF;
    }
    #pragma unroll
    for (int o = 16; o > 0; o >>= 1) m = fmaxf(m, __shfl_xor_sync(0xffffffffu, m, o));
    float s = 0.f;
    #pragma unroll
    for (int i = 0; i < 32; i++) {
        int q = lane + i * 32;
        if (q <= kt) { v[i] = __expf(v[i] - m); s += v[i]; }
    }
    #pragma unroll
    for (int o = 16; o > 0; o >>= 1) s += __shfl_xor_sync(0xffffffffu, s, o);
    const float inv = 1.0f / s;

    #pragma unroll
    for (int i = 0; i < 32; i++) {
        int q = lane + i * 32;
        if (q <= kt) {
            float w = v[i] * inv;
            tile[wid][q] = w;
            __nv_bfloat16 hi = __float2bfloat16(w);
            hrow[q] = hi;
            lrow[q] = __float2bfloat16(w - __bfloat162float(hi));
        } else {
            tile[wid][q] = 0.0f;
        }
    }
    const int qpad = ((kt >> 6) + 1) << 6;
    for (int q = kt + 1 + lane; q < qpad; q += 32) {
        hrow[q] = __float2bfloat16(0.f);
        lrow[q] = __float2bfloat16(0.f);
    }
    __syncthreads();

    // transposed write: wout[b,kt,q,h]; contiguous over (q, h within group)
    float* wo = wout + (size_t)bkt * TT * HH + hg * 8;
    #pragma unroll
    for (int idx = threadIdx.x; idx < 8192; idx += 256) {
        int q = idx >> 3, hl = idx & 7;
        wo[q * HH + hl] = tile[hl][q];
    }
}

// ---------------------------------------------------------------------------
// Tensor-core AV: attn[b,kt,h*64+j] = sum_q w[bh,kt,q] * V[b,q,h*64+j]
// 64(kt) x 64(j) per block, causal k-truncation, 3-term split.
// ---------------------------------------------------------------------------
__global__ __launch_bounds__(256)
void av_tc(const __nv_bfloat16* __restrict__ Whi, const __nv_bfloat16* __restrict__ Wlo,
           const __nv_bfloat16* __restrict__ Vhi, const __nv_bfloat16* __restrict__ Vlo,
           float* __restrict__ attn) {
    __shared__ __nv_bfloat16 sWhi[64 * LDS], sWlo[64 * LDS], sVhi[64 * LDS], sVlo[64 * LDS];
    const int bh = blockIdx.y;
    const int b = bh >> 4, h = bh & 15;
    const int m0 = blockIdx.x * 64;
    const int tid = threadIdx.x, wid = tid >> 5;
    const int warp_m = wid >> 1, warp_n = wid & 1;

    const __nv_bfloat16* Wh = Whi + (size_t)bh * TT * TT;
    const __nv_bfloat16* Wl = Wlo + (size_t)bh * TT * TT;
    const size_t vbase = (size_t)b * TT * DD + h * HDIM;

    wmma::fragment<wmma::accumulator, 16, 16, 16, float> acc[2];
    wmma::fill_fragment(acc[0], 0.0f);
    wmma::fill_fragment(acc[1], 0.0f);

    const int kend = m0 + 64;
    for (int q0 = 0; q0 < kend; q0 += 64) {
        #pragma unroll
        for (int u = tid; u < 512; u += 256) {
            int r = u >> 3, cq = u & 7;
            size_t offW = (size_t)(m0 + r) * TT + q0;
            *(uint4*)(&sWhi[r * LDS + cq * 8]) = ((const uint4*)(Wh + offW))[cq];
            *(uint4*)(&sWlo[r * LDS + cq * 8]) = ((const uint4*)(Wl + offW))[cq];
            *(uint4*)(&sVhi[r * LDS + cq * 8]) = ((const uint4*)(Vhi + vbase + (size_t)(q0 + r) * DD))[cq];
            *(uint4*)(&sVlo[r * LDS + cq * 8]) = ((const uint4*)(Vlo + vbase + (size_t)(q0 + r) * DD))[cq];
        }
        __syncthreads();
        #pragma unroll
        for (int kk = 0; kk < 64; kk += 16) {
            wmma::fragment<wmma::matrix_a, 16, 16, 16, __nv_bfloat16, wmma::row_major> aHi, aLo;
            wmma::fragment<wmma::matrix_b, 16, 16, 16, __nv_bfloat16, wmma::row_major> bHi[2], bLo[2];
            wmma::load_matrix_sync(aHi, &sWhi[(warp_m * 16) * LDS + kk], LDS);
            wmma::load_matrix_sync(aLo, &sWlo[(warp_m * 16) * LDS + kk], LDS);
            #pragma unroll
            for (int j = 0; j < 2; j++) {
                wmma::load_matrix_sync(bHi[j], &sVhi[kk * LDS + warp_n * 32 + j * 16], LDS);
                wmma::load_matrix_sync(bLo[j], &sVlo[kk * LDS + warp_n * 32 + j * 16], LDS);
            }
            #pragma unroll
            for (int j = 0; j < 2; j++) {
                wmma::mma_sync(acc[j], aHi, bHi[j], acc[j]);
                wmma::mma_sync(acc[j], aHi, bLo[j], acc[j]);
                wmma::mma_sync(acc[j], aLo, bHi[j], acc[j]);
            }
        }
        __syncthreads();
    }
    #pragma unroll
    for (int j = 0; j < 2; j++) {
        float* cp = attn + (size_t)(b * TT + m0 + warp_m * 16) * DD + h * HDIM
                         + warp_n * 32 + j * 16;
        wmma::store_matrix_sync(cp, acc[j], DD, wmma::mem_row_major);
    }
}

// ---------------------------------------------------------------------------
extern "C" void kernel_launch(void* const* d_in, const int* in_sizes, int n_in,
                              void* d_out, int out_size) {
    const float* x  = (const float*)d_in[0];
    const float* Wk = (const float*)d_in[4];
    const float* bk = (const float*)d_in[5];
    const float* Wq = (const float*)d_in[6];
    const float* bq = (const float*)d_in[7];
    const float* Wv = (const float*)d_in[8];
    const float* bv = (const float*)d_in[9];
    const float* Wp = (const float*)d_in[10];
    const float* bp = (const float*)d_in[11];

    float* out  = (float*)d_out;
    float* wout = out + (size_t)BT * DD;

    float *gk, *gq, *gv, *gs, *ga;
    __nv_bfloat16 *xhi, *xlo, *whi, *wlo, *ahi, *alo;
    __nv_bfloat16 *khi, *klo, *qhi, *qlo, *vhi, *vlo, *swhi, *swlo;
    cudaGetSymbolAddress((void**)&gk, g_k);
    cudaGetSymbolAddress((void**)&gq, g_q);
    cudaGetSymbolAddress((void**)&gv, g_v);
    cudaGetSymbolAddress((void**)&gs, g_s);
    cudaGetSymbolAddress((void**)&ga, g_attn);
    cudaGetSymbolAddress((void**)&xhi, g_xhi);
    cudaGetSymbolAddress((void**)&xlo, g_xlo);
    cudaGetSymbolAddress((void**)&whi, g_whi);
    cudaGetSymbolAddress((void**)&wlo, g_wlo);
    cudaGetSymbolAddress((void**)&ahi, g_ahi);
    cudaGetSymbolAddress((void**)&alo, g_alo);
    cudaGetSymbolAddress((void**)&khi, g_khi);
    cudaGetSymbolAddress((void**)&klo, g_klo);
    cudaGetSymbolAddress((void**)&qhi, g_qhi);
    cudaGetSymbolAddress((void**)&qlo, g_qlo);
    cudaGetSymbolAddress((void**)&vhi, g_vhi);
    cudaGetSymbolAddress((void**)&vlo, g_vlo);
    cudaGetSymbolAddress((void**)&swhi, g_swhi);
    cudaGetSymbolAddress((void**)&swlo, g_swlo);

    const size_t WSZ = (size_t)DD * DD;
    const int n4x = BT * DD / 4;
    const int n4w = DD * DD / 4;

    cvt_split<<<(n4x + 255) / 256, 256>>>(x,  xhi, xlo, n4x);
    cvt_split<<<(n4w + 255) / 256, 256>>>(Wk, whi + 0 * WSZ, wlo + 0 * WSZ, n4w);
    cvt_split<<<(n4w + 255) / 256, 256>>>(Wq, whi + 1 * WSZ, wlo + 1 * WSZ, n4w);
    cvt_split<<<(n4w + 255) / 256, 256>>>(Wv, whi + 2 * WSZ, wlo + 2 * WSZ, n4w);
    cvt_split<<<(n4w + 255) / 256, 256>>>(Wp, whi + 3 * WSZ, wlo + 3 * WSZ, n4w);

    dim3 ggrid(DD / 128, BT / 128);
    size_t gsm = 4 * 128 * LDT * sizeof(__nv_bfloat16);
    gemm_bf16split<<<ggrid, 256, gsm>>>(xhi, xlo, whi + 0 * WSZ, wlo + 0 * WSZ, gk, BT, DD, DD);
    gemm_bf16split<<<ggrid, 256, gsm>>>(xhi, xlo, whi + 1 * WSZ, wlo + 1 * WSZ, gq, BT, DD, DD);
    gemm_bf16split<<<ggrid, 256, gsm>>>(xhi, xlo, whi + 2 * WSZ, wlo + 2 * WSZ, gv, BT, DD, DD);

    bias_split<<<(n4x + 255) / 256, 256>>>(gk, bk, khi, klo, n4x);
    bias_split<<<(n4x + 255) / 256, 256>>>(gq, bq, qhi, qlo, n4x);
    bias_split<<<(n4x + 255) / 256, 256>>>(gv, bv, vhi, vlo, n4x);

    dim3 sc_grid(TT / 64, TT / 64, BB * HH);
    scores_tc<<<sc_grid, 256>>>(khi, klo, qhi, qlo, gs);

    dim3 sm_grid(2, BB * TT);
    fused_sm<<<sm_grid, 256>>>(gs, wout, swhi, swlo);

    dim3 av_grid(TT / 64, BB * HH);
    av_tc<<<av_grid, 256>>>(swhi, swlo, vhi, vlo, ga);

    cvt_split<<<(n4x + 255) / 256, 256>>>(ga, ahi, alo, n4x);
    gemm_bf16split<<<ggrid, 256, gsm>>>(ahi, alo, whi + 3 * WSZ, wlo + 3 * WSZ, out, BT, DD, DD);
    bias_add<<<(n4x + 255) / 256, 256>>>(out, bp, n4x);
}

// round 7
// speedup vs baseline: 2.9319x; 1.1621x over previous
#include <cuda_runtime.h>
#include <cuda_bf16.h>
#include <mma.h>
#include <math.h>
#include <cstdint>

using namespace nvcuda;

#define BB 4
#define TT 1024
#define DD 1024
#define HH 16
#define HDIM 64
#define BT (BB*TT)

// fp32 scratch
__device__ float g_s[(size_t)BB * HH * TT * TT];   // scores fp32 [b,h,kt,qt] (lower tri)

// bf16 split buffers
__device__ __nv_bfloat16 g_xhi[(size_t)BT * DD];
__device__ __nv_bfloat16 g_xlo[(size_t)BT * DD];
__device__ __nv_bfloat16 g_whi[(size_t)4 * DD * DD];
__device__ __nv_bfloat16 g_wlo[(size_t)4 * DD * DD];
__device__ __nv_bfloat16 g_ahi[(size_t)BT * DD];
__device__ __nv_bfloat16 g_alo[(size_t)BT * DD];
__device__ __nv_bfloat16 g_khi[(size_t)BT * DD];
__device__ __nv_bfloat16 g_klo[(size_t)BT * DD];
__device__ __nv_bfloat16 g_qhi[(size_t)BT * DD];
__device__ __nv_bfloat16 g_qlo[(size_t)BT * DD];
__device__ __nv_bfloat16 g_vhi[(size_t)BT * DD];
__device__ __nv_bfloat16 g_vlo[(size_t)BT * DD];
__device__ __nv_bfloat16 g_swhi[(size_t)BB * HH * TT * TT];
__device__ __nv_bfloat16 g_swlo[(size_t)BB * HH * TT * TT];

#define NEG_INF __int_as_float(0xff800000)

__device__ __forceinline__ void cpa16(void* sdst, const void* gsrc) {
    uint32_t s = (uint32_t)__cvta_generic_to_shared(sdst);
    asm volatile("cp.async.cg.shared.global [%0], [%1], 16;" :: "r"(s), "l"(gsrc));
}
__device__ __forceinline__ void cpa_commit() {
    asm volatile("cp.async.commit_group;");
}
template <int N> __device__ __forceinline__ void cpa_wait() {
    asm volatile("cp.async.wait_group %0;" :: "n"(N));
}

// ---------------------------------------------------------------------------
__global__ void cvt_split(const float* __restrict__ in,
                          __nv_bfloat16* __restrict__ hi,
                          __nv_bfloat16* __restrict__ lo, int n4) {
    int i = blockIdx.x * blockDim.x + threadIdx.x;
    if (i >= n4) return;
    float4 v = ((const float4*)in)[i];
    __nv_bfloat16 h0 = __float2bfloat16(v.x), h1 = __float2bfloat16(v.y);
    __nv_bfloat16 h2 = __float2bfloat16(v.z), h3 = __float2bfloat16(v.w);
    __nv_bfloat16 l0 = __float2bfloat16(v.x - __bfloat162float(h0));
    __nv_bfloat16 l1 = __float2bfloat16(v.y - __bfloat162float(h1));
    __nv_bfloat16 l2 = __float2bfloat16(v.z - __bfloat162float(h2));
    __nv_bfloat16 l3 = __float2bfloat16(v.w - __bfloat162float(h3));
    ((__nv_bfloat162*)hi)[2*i]   = __nv_bfloat162(h0, h1);
    ((__nv_bfloat162*)hi)[2*i+1] = __nv_bfloat162(h2, h3);
    ((__nv_bfloat162*)lo)[2*i]   = __nv_bfloat162(l0, l1);
    ((__nv_bfloat162*)lo)[2*i+1] = __nv_bfloat162(l2, l3);
}

// ---------------------------------------------------------------------------
// Pipelined split-bf16 GEMM: C = A @ W.T + bias.
// MODE 0: write fp32 C. MODE 1: write bf16 hi/lo split.
// 128x128 tile, BK=32, 2-stage cp.async double buffer, 8 warps.
// ---------------------------------------------------------------------------
#define LDT 48
#define STG (4 * 128 * LDT)   // bf16 elems per stage

template <int MODE>
__global__ __launch_bounds__(256, 1)
void gemm_pipe(const __nv_bfloat16* __restrict__ Ahi,
               const __nv_bfloat16* __restrict__ Alo,
               const __nv_bfloat16* __restrict__ Bhi,
               const __nv_bfloat16* __restrict__ Blo,
               const float* __restrict__ bias,
               float* __restrict__ Cf,
               __nv_bfloat16* __restrict__ Chi,
               __nv_bfloat16* __restrict__ Clo,
               int M, int N, int K) {
    extern __shared__ __nv_bfloat16 smem[];   // 2 stages * STG

    const int tid = threadIdx.x, wid = tid >> 5;
    const int warp_m = wid & 3, warp_n = wid >> 2;
    const int m0 = blockIdx.y * 128, n0 = blockIdx.x * 128;

    wmma::fragment<wmma::accumulator, 16, 16, 16, float> acc[2][4];
    #pragma unroll
    for (int i = 0; i < 2; i++)
        #pragma unroll
        for (int j = 0; j < 4; j++) wmma::fill_fragment(acc[i][j], 0.0f);

    auto load_stage = [&](int st, int k0) {
        __nv_bfloat16* base = smem + st * STG;
        __nv_bfloat16* sAhi = base;
        __nv_bfloat16* sAlo = base + 128 * LDT;
        __nv_bfloat16* sBhi = base + 2 * 128 * LDT;
        __nv_bfloat16* sBlo = base + 3 * 128 * LDT;
        #pragma unroll
        for (int u = tid; u < 512; u += 256) {
            int r = u >> 2, cq = u & 3;
            size_t offA = (size_t)(m0 + r) * K + k0 + cq * 8;
            size_t offB = (size_t)(n0 + r) * K + k0 + cq * 8;
            cpa16(&sAhi[r * LDT + cq * 8], Ahi + offA);
            cpa16(&sAlo[r * LDT + cq * 8], Alo + offA);
            cpa16(&sBhi[r * LDT + cq * 8], Bhi + offB);
            cpa16(&sBlo[r * LDT + cq * 8], Blo + offB);
        }
        cpa_commit();
    };

    const int nIter = K / 32;
    load_stage(0, 0);

    for (int i = 0; i < nIter; i++) {
        if (i + 1 < nIter) load_stage((i + 1) & 1, (i + 1) * 32);
        if (i + 1 < nIter) cpa_wait<1>(); else cpa_wait<0>();
        __syncthreads();

        __nv_bfloat16* base = smem + (i & 1) * STG;
        __nv_bfloat16* sAhi = base;
        __nv_bfloat16* sAlo = base + 128 * LDT;
        __nv_bfloat16* sBhi = base + 2 * 128 * LDT;
        __nv_bfloat16* sBlo = base + 3 * 128 * LDT;

        #pragma unroll
        for (int kk = 0; kk < 32; kk += 16) {
            wmma::fragment<wmma::matrix_a, 16, 16, 16, __nv_bfloat16, wmma::row_major> aHi[2], aLo[2];
            wmma::fragment<wmma::matrix_b, 16, 16, 16, __nv_bfloat16, wmma::col_major> bHi[4], bLo[4];
            #pragma unroll
            for (int ii = 0; ii < 2; ii++) {
                wmma::load_matrix_sync(aHi[ii], &sAhi[(warp_m * 32 + ii * 16) * LDT + kk], LDT);
                wmma::load_matrix_sync(aLo[ii], &sAlo[(warp_m * 32 + ii * 16) * LDT + kk], LDT);
            }
            #pragma unroll
            for (int j = 0; j < 4; j++) {
                wmma::load_matrix_sync(bHi[j], &sBhi[(warp_n * 64 + j * 16) * LDT + kk], LDT);
                wmma::load_matrix_sync(bLo[j], &sBlo[(warp_n * 64 + j * 16) * LDT + kk], LDT);
            }
            #pragma unroll
            for (int ii = 0; ii < 2; ii++)
                #pragma unroll
                for (int j = 0; j < 4; j++) {
                    wmma::mma_sync(acc[ii][j], aHi[ii], bHi[j], acc[ii][j]);
                    wmma::mma_sync(acc[ii][j], aHi[ii], bLo[j], acc[ii][j]);
                    wmma::mma_sync(acc[ii][j], aLo[ii], bHi[j], acc[ii][j]);
                }
        }
        __syncthreads();
    }

    // Epilogue: stage accumulators in smem, add bias, write out.
    float* sC = (float*)smem;   // 128 x 132
    #pragma unroll
    for (int ii = 0; ii < 2; ii++)
        #pragma unroll
        for (int j = 0; j < 4; j++)
            wmma::store_matrix_sync(&sC[(warp_m * 32 + ii * 16) * 132 + warp_n * 64 + j * 16],
                                    acc[ii][j], 132, wmma::mem_row_major);
    __syncthreads();

    #pragma unroll
    for (int it = 0; it < 16; it++) {
        int idx = tid + it * 256;            // 0..4095
        int r = idx >> 5, c4 = idx & 31;
        float4 v = *(float4*)&sC[r * 132 + c4 * 4];
        float4 bb = *(const float4*)&bias[n0 + c4 * 4];
        v.x += bb.x; v.y += bb.y; v.z += bb.z; v.w += bb.w;
        size_t off = (size_t)(m0 + r) * N + n0 + c4 * 4;
        if (MODE == 0) {
            *(float4*)&Cf[off] = v;
        } else {
            __nv_bfloat16 h0 = __float2bfloat16(v.x), h1 = __float2bfloat16(v.y);
            __nv_bfloat16 h2 = __float2bfloat16(v.z), h3 = __float2bfloat16(v.w);
            __nv_bfloat16 l0 = __float2bfloat16(v.x - __bfloat162float(h0));
            __nv_bfloat16 l1 = __float2bfloat16(v.y - __bfloat162float(h1));
            __nv_bfloat16 l2 = __float2bfloat16(v.z - __bfloat162float(h2));
            __nv_bfloat16 l3 = __float2bfloat16(v.w - __bfloat162float(h3));
            ((__nv_bfloat162*)(Chi + off))[0] = __nv_bfloat162(h0, h1);
            ((__nv_bfloat162*)(Chi + off))[1] = __nv_bfloat162(h2, h3);
            ((__nv_bfloat162*)(Clo + off))[0] = __nv_bfloat162(l0, l1);
            ((__nv_bfloat162*)(Clo + off))[1] = __nv_bfloat162(l2, l3);
        }
    }
}

// ---------------------------------------------------------------------------
// Tensor-core scores (lower-tri blocks only)
// ---------------------------------------------------------------------------
#define LDS 72
__global__ __launch_bounds__(256)
void scores_tc(const __nv_bfloat16* __restrict__ Khi, const __nv_bfloat16* __restrict__ Klo,
               const __nv_bfloat16* __restrict__ Qhi, const __nv_bfloat16* __restrict__ Qlo,
               float* __restrict__ S) {
    if (blockIdx.x > blockIdx.y) return;
    __shared__ __nv_bfloat16 sKhi[64 * LDS], sKlo[64 * LDS], sQhi[64 * LDS], sQlo[64 * LDS];
    const int bh = blockIdx.z;
    const int b = bh >> 4, h = bh & 15;
    const int kt0 = blockIdx.y * 64, qt0 = blockIdx.x * 64;
    const int tid = threadIdx.x, wid = tid >> 5;
    const int warp_m = wid >> 1, warp_n = wid & 1;

    const size_t baseK = (size_t)(b * TT + kt0) * DD + h * HDIM;
    const size_t baseQ = (size_t)(b * TT + qt0) * DD + h * HDIM;
    #pragma unroll
    for (int u = tid; u < 512; u += 256) {
        int r = u >> 3, cq = u & 7;
        *(uint4*)(&sKhi[r * LDS + cq * 8]) = ((const uint4*)(Khi + baseK + (size_t)r * DD))[cq];
        *(uint4*)(&sKlo[r * LDS + cq * 8]) = ((const uint4*)(Klo + baseK + (size_t)r * DD))[cq];
        *(uint4*)(&sQhi[r * LDS + cq * 8]) = ((const uint4*)(Qhi + baseQ + (size_t)r * DD))[cq];
        *(uint4*)(&sQlo[r * LDS + cq * 8]) = ((const uint4*)(Qlo + baseQ + (size_t)r * DD))[cq];
    }
    __syncthreads();

    wmma::fragment<wmma::accumulator, 16, 16, 16, float> acc[2];
    wmma::fill_fragment(acc[0], 0.0f);
    wmma::fill_fragment(acc[1], 0.0f);

    #pragma unroll
    for (int kk = 0; kk < 64; kk += 16) {
        wmma::fragment<wmma::matrix_a, 16, 16, 16, __nv_bfloat16, wmma::row_major> aHi, aLo;
        wmma::fragment<wmma::matrix_b, 16, 16, 16, __nv_bfloat16, wmma::col_major> bHi[2], bLo[2];
        wmma::load_matrix_sync(aHi, &sKhi[(warp_m * 16) * LDS + kk], LDS);
        wmma::load_matrix_sync(aLo, &sKlo[(warp_m * 16) * LDS + kk], LDS);
        #pragma unroll
        for (int j = 0; j < 2; j++) {
            wmma::load_matrix_sync(bHi[j], &sQhi[(warp_n * 32 + j * 16) * LDS + kk], LDS);
            wmma::load_matrix_sync(bLo[j], &sQlo[(warp_n * 32 + j * 16) * LDS + kk], LDS);
        }
        #pragma unroll
        for (int j = 0; j < 2; j++) {
            wmma::mma_sync(acc[j], aHi, bHi[j], acc[j]);
            wmma::mma_sync(acc[j], aHi, bLo[j], acc[j]);
            wmma::mma_sync(acc[j], aLo, bHi[j], acc[j]);
        }
    }
    #pragma unroll
    for (int j = 0; j < 2; j++) {
        #pragma unroll
        for (int e = 0; e < acc[j].num_elements; e++) acc[j].x[e] *= 0.03125f;
        float* sp = S + (size_t)bh * TT * TT + (size_t)(kt0 + warp_m * 16) * TT
                      + qt0 + warp_n * 32 + j * 16;
        wmma::store_matrix_sync(sp, acc[j], TT, wmma::mem_row_major);
    }
}

// ---------------------------------------------------------------------------
// Fused masked softmax + transposed wout + bf16 split weights
// ---------------------------------------------------------------------------
__global__ __launch_bounds__(256)
void fused_sm(const float* __restrict__ S, float* __restrict__ wout,
              __nv_bfloat16* __restrict__ whi, __nv_bfloat16* __restrict__ wlo) {
    __shared__ float tile[8][1032];
    const int bkt = blockIdx.y;
    const int b = bkt >> 10, kt = bkt & 1023;
    const int hg = blockIdx.x;
    const int wid = threadIdx.x >> 5, lane = threadIdx.x & 31;
    const int h = hg * 8 + wid;

    const size_t rowoff = ((size_t)(b * HH + h) * TT + kt) * TT;
    const float* row = S + rowoff;
    __nv_bfloat16* hrow = whi + rowoff;
    __nv_bfloat16* lrow = wlo + rowoff;

    float v[32];
    float m = NEG_INF;
    #pragma unroll
    for (int i = 0; i < 32; i++) {
        int q = lane + i * 32;
        if (q <= kt) { v[i] = row[q]; m = fmaxf(m, v[i]); }
        else v[i] = NEG_INF;
    }
    #pragma unroll
    for (int o = 16; o > 0; o >>= 1) m = fmaxf(m, __shfl_xor_sync(0xffffffffu, m, o));
    float s = 0.f;
    #pragma unroll
    for (int i = 0; i < 32; i++) {
        int q = lane + i * 32;
        if (q <= kt) { v[i] = __expf(v[i] - m); s += v[i]; }
    }
    #pragma unroll
    for (int o = 16; o > 0; o >>= 1) s += __shfl_xor_sync(0xffffffffu, s, o);
    const float inv = 1.0f / s;

    #pragma unroll
    for (int i = 0; i < 32; i++) {
        int q = lane + i * 32;
        if (q <= kt) {
            float w = v[i] * inv;
            tile[wid][q] = w;
            __nv_bfloat16 hi = __float2bfloat16(w);
            hrow[q] = hi;
            lrow[q] = __float2bfloat16(w - __bfloat162float(hi));
        } else {
            tile[wid][q] = 0.0f;
        }
    }
    const int qpad = ((kt >> 6) + 1) << 6;
    for (int q = kt + 1 + lane; q < qpad; q += 32) {
        hrow[q] = __float2bfloat16(0.f);
        lrow[q] = __float2bfloat16(0.f);
    }
    __syncthreads();

    float* wo = wout + (size_t)bkt * TT * HH + hg * 8;
    #pragma unroll
    for (int idx = threadIdx.x; idx < 8192; idx += 256) {
        int q = idx >> 3, hl = idx & 7;
        wo[q * HH + hl] = tile[hl][q];
    }
}

// ---------------------------------------------------------------------------
// Tensor-core AV with split epilogue -> ahi/alo (no fp32 round-trip)
// ---------------------------------------------------------------------------
__global__ __launch_bounds__(256)
void av_tc(const __nv_bfloat16* __restrict__ Whi, const __nv_bfloat16* __restrict__ Wlo,
           const __nv_bfloat16* __restrict__ Vhi, const __nv_bfloat16* __restrict__ Vlo,
           __nv_bfloat16* __restrict__ Ahi, __nv_bfloat16* __restrict__ Alo) {
    __shared__ __align__(16) char smraw[4 * 64 * LDS * 2];
    __nv_bfloat16* sWhi = (__nv_bfloat16*)smraw;
    __nv_bfloat16* sWlo = sWhi + 64 * LDS;
    __nv_bfloat16* sVhi = sWlo + 64 * LDS;
    __nv_bfloat16* sVlo = sVhi + 64 * LDS;

    const int bh = blockIdx.y;
    const int b = bh >> 4, h = bh & 15;
    const int m0 = blockIdx.x * 64;
    const int tid = threadIdx.x, wid = tid >> 5;
    const int warp_m = wid >> 1, warp_n = wid & 1;

    const __nv_bfloat16* Wh = Whi + (size_t)bh * TT * TT;
    const __nv_bfloat16* Wl = Wlo + (size_t)bh * TT * TT;
    const size_t vbase = (size_t)b * TT * DD + h * HDIM;

    wmma::fragment<wmma::accumulator, 16, 16, 16, float> acc[2];
    wmma::fill_fragment(acc[0], 0.0f);
    wmma::fill_fragment(acc[1], 0.0f);

    const int kend = m0 + 64;
    for (int q0 = 0; q0 < kend; q0 += 64) {
        #pragma unroll
        for (int u = tid; u < 512; u += 256) {
            int r = u >> 3, cq = u & 7;
            size_t offW = (size_t)(m0 + r) * TT + q0;
            *(uint4*)(&sWhi[r * LDS + cq * 8]) = ((const uint4*)(Wh + offW))[cq];
            *(uint4*)(&sWlo[r * LDS + cq * 8]) = ((const uint4*)(Wl + offW))[cq];
            *(uint4*)(&sVhi[r * LDS + cq * 8]) = ((const uint4*)(Vhi + vbase + (size_t)(q0 + r) * DD))[cq];
            *(uint4*)(&sVlo[r * LDS + cq * 8]) = ((const uint4*)(Vlo + vbase + (size_t)(q0 + r) * DD))[cq];
        }
        __syncthreads();
        #pragma unroll
        for (int kk = 0; kk < 64; kk += 16) {
            wmma::fragment<wmma::matrix_a, 16, 16, 16, __nv_bfloat16, wmma::row_major> aHi, aLo;
            wmma::fragment<wmma::matrix_b, 16, 16, 16, __nv_bfloat16, wmma::row_major> bHi[2], bLo[2];
            wmma::load_matrix_sync(aHi, &sWhi[(warp_m * 16) * LDS + kk], LDS);
            wmma::load_matrix_sync(aLo, &sWlo[(warp_m * 16) * LDS + kk], LDS);
            #pragma unroll
            for (int j = 0; j < 2; j++) {
                wmma::load_matrix_sync(bHi[j], &sVhi[kk * LDS + warp_n * 32 + j * 16], LDS);
                wmma::load_matrix_sync(bLo[j], &sVlo[kk * LDS + warp_n * 32 + j * 16], LDS);
            }
            #pragma unroll
            for (int j = 0; j < 2; j++) {
                wmma::mma_sync(acc[j], aHi, bHi[j], acc[j]);
                wmma::mma_sync(acc[j], aHi, bLo[j], acc[j]);
                wmma::mma_sync(acc[j], aLo, bHi[j], acc[j]);
            }
        }
        __syncthreads();
    }

    // epilogue: stage fp32 in smem, split-write bf16 hi/lo
    float* sC = (float*)smraw;   // 64 x 68
    #pragma unroll
    for (int j = 0; j < 2; j++)
        wmma::store_matrix_sync(&sC[(warp_m * 16) * 68 + warp_n * 32 + j * 16],
                                acc[j], 68, wmma::mem_row_major);
    __syncthreads();

    #pragma unroll
    for (int it = 0; it < 4; it++) {
        int idx = tid + it * 256;            // 0..1023
        int r = idx >> 4, c4 = idx & 15;
        float4 v = *(float4*)&sC[r * 68 + c4 * 4];
        size_t off = (size_t)(b * TT + m0 + r) * DD + h * HDIM + c4 * 4;
        __nv_bfloat16 h0 = __float2bfloat16(v.x), h1 = __float2bfloat16(v.y);
        __nv_bfloat16 h2 = __float2bfloat16(v.z), h3 = __float2bfloat16(v.w);
        __nv_bfloat16 l0 = __float2bfloat16(v.x - __bfloat162float(h0));
        __nv_bfloat16 l1 = __float2bfloat16(v.y - __bfloat162float(h1));
        __nv_bfloat16 l2 = __float2bfloat16(v.z - __bfloat162float(h2));
        __nv_bfloat16 l3 = __float2bfloat16(v.w - __bfloat162float(h3));
        ((__nv_bfloat162*)(Ahi + off))[0] = __nv_bfloat162(h0, h1);
        ((__nv_bfloat162*)(Ahi + off))[1] = __nv_bfloat162(h2, h3);
        ((__nv_bfloat162*)(Alo + off))[0] = __nv_bfloat162(l0, l1);
        ((__nv_bfloat162*)(Alo + off))[1] = __nv_bfloat162(l2, l3);
    }
}

// ---------------------------------------------------------------------------
extern "C" void kernel_launch(void* const* d_in, const int* in_sizes, int n_in,
                              void* d_out, int out_size) {
    const float* x  = (const float*)d_in[0];
    const float* Wk = (const float*)d_in[4];
    const float* bk = (const float*)d_in[5];
    const float* Wq = (const float*)d_in[6];
    const float* bq = (const float*)d_in[7];
    const float* Wv = (const float*)d_in[8];
    const float* bv = (const float*)d_in[9];
    const float* Wp = (const float*)d_in[10];
    const float* bp = (const float*)d_in[11];

    float* out  = (float*)d_out;
    float* wout = out + (size_t)BT * DD;

    float *gs;
    __nv_bfloat16 *xhi, *xlo, *whi, *wlo, *ahi, *alo;
    __nv_bfloat16 *khi, *klo, *qhi, *qlo, *vhi, *vlo, *swhi, *swlo;
    cudaGetSymbolAddress((void**)&gs, g_s);
    cudaGetSymbolAddress((void**)&xhi, g_xhi);
    cudaGetSymbolAddress((void**)&xlo, g_xlo);
    cudaGetSymbolAddress((void**)&whi, g_whi);
    cudaGetSymbolAddress((void**)&wlo, g_wlo);
    cudaGetSymbolAddress((void**)&ahi, g_ahi);
    cudaGetSymbolAddress((void**)&alo, g_alo);
    cudaGetSymbolAddress((void**)&khi, g_khi);
    cudaGetSymbolAddress((void**)&klo, g_klo);
    cudaGetSymbolAddress((void**)&qhi, g_qhi);
    cudaGetSymbolAddress((void**)&qlo, g_qlo);
    cudaGetSymbolAddress((void**)&vhi, g_vhi);
    cudaGetSymbolAddress((void**)&vlo, g_vlo);
    cudaGetSymbolAddress((void**)&swhi, g_swhi);
    cudaGetSymbolAddress((void**)&swlo, g_swlo);

    const size_t WSZ = (size_t)DD * DD;
    const int n4x = BT * DD / 4;
    const int n4w = DD * DD / 4;

    const size_t gsm = (size_t)2 * STG * sizeof(__nv_bfloat16);   // 98304
    cudaFuncSetAttribute(gemm_pipe<0>, cudaFuncAttributeMaxDynamicSharedMemorySize, (int)gsm);
    cudaFuncSetAttribute(gemm_pipe<1>, cudaFuncAttributeMaxDynamicSharedMemorySize, (int)gsm);

    cvt_split<<<(n4x + 255) / 256, 256>>>(x,  xhi, xlo, n4x);
    cvt_split<<<(n4w + 255) / 256, 256>>>(Wk, whi + 0 * WSZ, wlo + 0 * WSZ, n4w);
    cvt_split<<<(n4w + 255) / 256, 256>>>(Wq, whi + 1 * WSZ, wlo + 1 * WSZ, n4w);
    cvt_split<<<(n4w + 255) / 256, 256>>>(Wv, whi + 2 * WSZ, wlo + 2 * WSZ, n4w);
    cvt_split<<<(n4w + 255) / 256, 256>>>(Wp, whi + 3 * WSZ, wlo + 3 * WSZ, n4w);

    dim3 ggrid(DD / 128, BT / 128);
    gemm_pipe<1><<<ggrid, 256, gsm>>>(xhi, xlo, whi + 0 * WSZ, wlo + 0 * WSZ, bk,
                                      nullptr, khi, klo, BT, DD, DD);
    gemm_pipe<1><<<ggrid, 256, gsm>>>(xhi, xlo, whi + 1 * WSZ, wlo + 1 * WSZ, bq,
                                      nullptr, qhi, qlo, BT, DD, DD);
    gemm_pipe<1><<<ggrid, 256, gsm>>>(xhi, xlo, whi + 2 * WSZ, wlo + 2 * WSZ, bv,
                                      nullptr, vhi, vlo, BT, DD, DD);

    dim3 sc_grid(TT / 64, TT / 64, BB * HH);
    scores_tc<<<sc_grid, 256>>>(khi, klo, qhi, qlo, gs);

    dim3 sm_grid(2, BB * TT);
    fused_sm<<<sm_grid, 256>>>(gs, wout, swhi, swlo);

    dim3 av_grid(TT / 64, BB * HH);
    av_tc<<<av_grid, 256>>>(swhi, swlo, vhi, vlo, ahi, alo);

    gemm_pipe<0><<<ggrid, 256, gsm>>>(ahi, alo, whi + 3 * WSZ, wlo + 3 * WSZ, bp,
                                      out, nullptr, nullptr, BT, DD, DD);
}